// round 10
// baseline (speedup 1.0000x reference)
#include <cuda_runtime.h>
#include <cuda_fp16.h>
#include <cstdint>

#define BDIM 16384
#define HDIM 1024
constexpr size_t NBH = (size_t)BDIM * HDIM;
constexpr size_t NHH = (size_t)HDIM * HDIM;

// ---------------------------------------------------------------------------
// Scratch (static device arrays: allocation-free per harness rules)
// ---------------------------------------------------------------------------
__device__ __align__(16) __half g_kh[NBH];
__device__ __align__(16) __half g_vh[NBH];
__device__ __align__(16) __half g_rh[NBH];

__device__ __align__(16) __half g_xk[NBH];
__device__ __align__(16) __half g_xv[NBH];
__device__ __align__(16) __half g_xr[NBH];
__device__ __align__(16) __half g_rw[NBH];

__device__ __align__(16) __half g_wk[NHH];
__device__ __align__(16) __half g_wv[NHH];
__device__ __align__(16) __half g_wr[NHH];
__device__ __align__(16) __half g_wo[NHH];

// ---------------------------------------------------------------------------
// PTX helpers (legal on base sm_103 target)
// ---------------------------------------------------------------------------
__device__ __forceinline__ uint32_t smem_u32(const void* p) {
    uint32_t a;
    asm("{ .reg .u64 t; cvta.to.shared.u64 t, %1; cvt.u32.u64 %0, t; }" : "=r"(a) : "l"(p));
    return a;
}
__device__ __forceinline__ void cp16(uint32_t dst, const void* src) {
    asm volatile("cp.async.cg.shared.global [%0], [%1], 16;" :: "r"(dst), "l"(src) : "memory");
}
__device__ __forceinline__ void cp_commit() {
    asm volatile("cp.async.commit_group;" ::: "memory");
}
__device__ __forceinline__ void ldsm4(uint32_t* r, uint32_t addr) {
    asm volatile("ldmatrix.sync.aligned.m8n8.x4.shared.b16 {%0,%1,%2,%3}, [%4];"
                 : "=r"(r[0]), "=r"(r[1]), "=r"(r[2]), "=r"(r[3]) : "r"(addr));
}
__device__ __forceinline__ void mma_f16(float* c, const uint32_t* a, uint32_t b0, uint32_t b1) {
    asm volatile(
        "mma.sync.aligned.m16n8k16.row.col.f32.f16.f16.f32 "
        "{%0,%1,%2,%3}, {%4,%5,%6,%7}, {%8,%9}, {%0,%1,%2,%3};"
        : "+f"(c[0]), "+f"(c[1]), "+f"(c[2]), "+f"(c[3])
        : "r"(a[0]), "r"(a[1]), "r"(a[2]), "r"(a[3]), "r"(b0), "r"(b1));
}

// ---------------------------------------------------------------------------
// GEMM config: CTA 256x128x64, 16 warps (8m x 2n -> warp tile 32x64), 4 stages
// 512 threads, 1 CTA/SM (full 64K-register file), 16 warps/SM as before.
// ---------------------------------------------------------------------------
constexpr int BM = 256, BN = 128, BK = 64;
constexpr int GT = 512;
constexpr int NCH = HDIM / BK;              // 16
constexpr int NSTG = 4;
constexpr int A_PLANE_B = BM * BK * 2;      // 32768
constexpr int B_PLANE_B = BN * BK * 2;      // 16384
constexpr int STAGE_B = A_PLANE_B + B_PLANE_B;  // 49152
constexpr int SMEM_TOT = NSTG * STAGE_B;    // 196608

// SW128: row stride 128B (8 x 16B chunks), chunk swizzled by row&7
__device__ __forceinline__ uint32_t swz_off(int row, int ch) {
    return (uint32_t)(row * 128 + ((ch ^ (row & 7)) << 4));
}

// ---------------------------------------------------------------------------
// fp16 GEMM: D[M,N] = A[M,K] @ W[N,K]^T
// which = base + blockIdx.z: 0=k, 1=v, 2=r (fp16 out), 3=out (fp32 out)
// Inner compute loop structure identical to R5/R9 (short fragment lifetimes).
// ---------------------------------------------------------------------------
template <bool FP16OUT>
__global__ void __launch_bounds__(GT, 1) gemm_mma(int base_which, float* __restrict__ outp)
{
    extern __shared__ __align__(1024) char smem[];
    const uint32_t sb = smem_u32(smem);
    const int tid = threadIdx.x;
    const int lane = tid & 31;
    const int warp = tid >> 5;
    const int wm = warp >> 1;              // 0..7
    const int wn = warp & 1;               // 0..1
    const int m0 = blockIdx.y * BM;
    const int n0 = blockIdx.x * BN;

    const int which = base_which + blockIdx.z;
    const __half *A, *B;
    __half* Dh = nullptr;
    float* Df = nullptr;
    if (which == 0)      { A = g_xk; B = g_wk; Dh = g_kh; }
    else if (which == 1) { A = g_xv; B = g_wv; Dh = g_vh; }
    else if (which == 2) { A = g_xr; B = g_wr; Dh = g_rh; }
    else                 { A = g_rw; B = g_wo; Df = outp; }

    float acc[2][8][4];
#pragma unroll
    for (int i = 0; i < 2; i++)
#pragma unroll
        for (int j = 0; j < 8; j++)
#pragma unroll
            for (int l = 0; l < 4; l++) acc[i][j][l] = 0.f;

    auto fill = [&](int c) {
        const uint32_t base = sb + (c % NSTG) * STAGE_B;
        const int kt = c * BK;
        // A: 256 rows x 8 chunks = 2048 -> 4 per thread
#pragma unroll
        for (int it = 0; it < 4; it++) {
            int q = it * GT + tid;
            int row = q >> 3;
            int ch = q & 7;
            const void* src = A + (size_t)(m0 + row) * HDIM + kt + ch * 8;
            cp16(base + swz_off(row, ch), src);
        }
        // B: 128 rows x 8 chunks = 1024 -> 2 per thread
#pragma unroll
        for (int it = 0; it < 2; it++) {
            int q = it * GT + tid;
            int row = q >> 3;
            int ch = q & 7;
            const void* src = B + (size_t)(n0 + row) * HDIM + kt + ch * 8;
            cp16(base + A_PLANE_B + swz_off(row, ch), src);
        }
        cp_commit();
    };

    // ldmatrix lane-address components (proven layout)
    const int lr = lane & 7;
    const int a_row_base = wm * 32 + ((lane >> 3) & 1) * 8 + lr;   // + i*16
    const int a_ch_base  = (lane >> 4);                            // + 2*kk
    const int b_row_base = wn * 64 + (lane >> 4) * 8 + lr;         // + jj*16
    const int b_ch_base  = ((lane >> 3) & 1);                      // + 2*kk

    auto compute = [&](int c) {
        const uint32_t base = sb + (c % NSTG) * STAGE_B;
#pragma unroll
        for (int kk = 0; kk < 4; kk++) {
            uint32_t A4[2][4];
#pragma unroll
            for (int i = 0; i < 2; i++) {
                int row = a_row_base + i * 16;
                ldsm4(A4[i], base + swz_off(row, a_ch_base + 2 * kk));
            }
#pragma unroll
            for (int jj = 0; jj < 4; jj++) {
                int rowb = b_row_base + jj * 16;
                uint32_t B4[4];
                ldsm4(B4, base + A_PLANE_B + swz_off(rowb, b_ch_base + 2 * kk));
#pragma unroll
                for (int i = 0; i < 2; i++) {
                    mma_f16(acc[i][2 * jj],     A4[i], B4[0], B4[1]);
                    mma_f16(acc[i][2 * jj + 1], A4[i], B4[2], B4[3]);
                }
            }
        }
    };

    // ---- 4-stage pipeline, prefetch depth 3 ----
    fill(0);
    fill(1);
    fill(2);
    for (int c = 0; c < NCH; c++) {
        if (c < NCH - 2)      asm volatile("cp.async.wait_group 2;" ::: "memory");
        else if (c == NCH - 2) asm volatile("cp.async.wait_group 1;" ::: "memory");
        else                  asm volatile("cp.async.wait_group 0;" ::: "memory");
        __syncthreads();
        if (c + 3 < NCH) fill(c + 3);
        compute(c);
    }

    // ---- epilogue ----
#pragma unroll
    for (int i = 0; i < 2; i++) {
        int row = m0 + wm * 32 + i * 16 + (lane >> 2);
#pragma unroll
        for (int j = 0; j < 8; j++) {
            int col = n0 + wn * 64 + j * 8 + (lane & 3) * 2;
            if (FP16OUT) {
                *(__half2*)(Dh + (size_t)row * HDIM + col) =
                    __floats2half2_rn(acc[i][j][0], acc[i][j][1]);
                *(__half2*)(Dh + (size_t)(row + 8) * HDIM + col) =
                    __floats2half2_rn(acc[i][j][2], acc[i][j][3]);
            } else {
                float2 v0 = { acc[i][j][0], acc[i][j][1] };
                float2 v1 = { acc[i][j][2], acc[i][j][3] };
                *(float2*)(Df + (size_t)row * HDIM + col)       = v0;
                *(float2*)(Df + (size_t)(row + 8) * HDIM + col) = v1;
            }
        }
    }
}

// ---------------------------------------------------------------------------
// prep: blend token-shift mixes -> fp16 planes; also copy x -> out slot 1
// ---------------------------------------------------------------------------
__device__ __forceinline__ void blend_store(
    const float4& xv, const float4& av, const float4& m, __half* dst, size_t i)
{
    union { __half h[4]; uint2 u; } H;
    H.h[0] = __float2half_rn(xv.x * m.x + av.x * (1.f - m.x));
    H.h[1] = __float2half_rn(xv.y * m.y + av.y * (1.f - m.y));
    H.h[2] = __float2half_rn(xv.z * m.z + av.z * (1.f - m.z));
    H.h[3] = __float2half_rn(xv.w * m.w + av.w * (1.f - m.w));
    *(uint2*)(dst + i) = H.u;
}

__global__ void __launch_bounds__(256) prep_act(
    const float* __restrict__ x, const float* __restrict__ alpha,
    const float* __restrict__ mk, const float* __restrict__ mv,
    const float* __restrict__ mr, float* __restrict__ out)
{
    size_t i = ((size_t)blockIdx.x * 256 + threadIdx.x) * 4;
    int h = (int)(i & (HDIM - 1));
    float4 xv = *(const float4*)(x + i);
    float4 av = *(const float4*)(alpha + i);
    blend_store(xv, av, *(const float4*)(mk + h), g_xk, i);
    blend_store(xv, av, *(const float4*)(mv + h), g_xv, i);
    blend_store(xv, av, *(const float4*)(mr + h), g_xr, i);
    *(float4*)(out + NBH + i) = xv;   // slot 1: x passthrough
}

__global__ void __launch_bounds__(256) prep_w(
    const float* __restrict__ Wk, const float* __restrict__ Wv,
    const float* __restrict__ Wr, const float* __restrict__ Wo)
{
    const float* W;
    __half* hp;
    switch (blockIdx.y) {
        case 0: W = Wk; hp = g_wk; break;
        case 1: W = Wv; hp = g_wv; break;
        case 2: W = Wr; hp = g_wr; break;
        default: W = Wo; hp = g_wo; break;
    }
    size_t i = ((size_t)blockIdx.x * 256 + threadIdx.x) * 4;
    float4 w = *(const float4*)(W + i);
    union { __half h[4]; uint2 u; } H;
    H.h[0] = __float2half_rn(w.x);
    H.h[1] = __float2half_rn(w.y);
    H.h[2] = __float2half_rn(w.z);
    H.h[3] = __float2half_rn(w.w);
    *(uint2*)(hp + i) = H.u;
}

// ---------------------------------------------------------------------------
// Fused elementwise WKV + state update + r*wkv (fp16) + output stores
// ---------------------------------------------------------------------------
__global__ void __launch_bounds__(256) ew_kernel(
    const float* __restrict__ aa, const float* __restrict__ bb,
    const float* __restrict__ pp, const float* __restrict__ td,
    const float* __restrict__ tf, float* __restrict__ out)
{
    size_t i4 = (size_t)blockIdx.x * 256 + threadIdx.x;
    size_t i = i4 * 4;
    int h = (int)(i & (HDIM - 1));

    union { uint2 u; __half hh[4]; } KU, VU, RU;
    KU.u = *(const uint2*)(g_kh + i);
    VU.u = *(const uint2*)(g_vh + i);
    RU.u = *(const uint2*)(g_rh + i);

    float4 p4 = *(const float4*)(pp + i);
    float4 a4 = *(const float4*)(aa + i);
    float4 b4 = *(const float4*)(bb + i);
    float4 tf4 = *(const float4*)(tf + h);
    float4 td4 = *(const float4*)(td + h);

    float4 na4, nb4, q24;
    float* p = &p4.x;  float* a = &a4.x;  float* b = &b4.x;
    float* tff = &tf4.x; float* tdd = &td4.x;
    float* na = &na4.x; float* nb = &nb4.x; float* q2 = &q24.x;

    union { __half hh[4]; uint2 u; } RW;

#pragma unroll
    for (int j = 0; j < 4; j++) {
        float kk = __half2float(KU.hh[j]);
        float vv = __half2float(VU.hh[j]);
        float rp = __half2float(RU.hh[j]);
        float ww = tff[j] + kk;
        float qq = fmaxf(p[j], ww);
        float e1 = expf(p[j] - qq);
        float e2 = expf(ww - qq);
        float wkv = (e1 * a[j] + e2 * vv) / (e1 * b[j] + e2);
        float w2 = p[j] + tdd[j];
        float qb = fmaxf(w2, kk);
        float e1b = expf(w2 - qb);
        float e2b = expf(kk - qb);
        na[j] = e1b * a[j] + e2b * vv;
        nb[j] = e1b * b[j] + e2b;
        q2[j] = qb;
        float r = 1.f / (1.f + expf(-rp));
        RW.hh[j] = __float2half_rn(r * wkv);
    }

    *(uint2*)(g_rw + i) = RW.u;
    *(float4*)(out + 2 * NBH + i) = na4;  // slot 2: next_aa
    *(float4*)(out + 3 * NBH + i) = nb4;  // slot 3: next_bb
    *(float4*)(out + 4 * NBH + i) = q24;  // slot 4: qq2
}

// ---------------------------------------------------------------------------
extern "C" void kernel_launch(void* const* d_in, const int* in_sizes, int n_in,
                              void* d_out, int out_size)
{
    const float* x     = (const float*)d_in[0];
    const float* alpha = (const float*)d_in[1];
    const float* aa    = (const float*)d_in[2];
    const float* bb    = (const float*)d_in[3];
    const float* pp    = (const float*)d_in[4];
    const float* td    = (const float*)d_in[5];
    const float* tf    = (const float*)d_in[6];
    const float* mk    = (const float*)d_in[7];
    const float* mv    = (const float*)d_in[8];
    const float* mr    = (const float*)d_in[9];
    const float* Wk    = (const float*)d_in[10];
    const float* Wv    = (const float*)d_in[11];
    const float* Wr    = (const float*)d_in[12];
    const float* Wo    = (const float*)d_in[13];
    float* out = (float*)d_out;

    cudaFuncSetAttribute(gemm_mma<true>,  cudaFuncAttributeMaxDynamicSharedMemorySize, SMEM_TOT);
    cudaFuncSetAttribute(gemm_mma<false>, cudaFuncAttributeMaxDynamicSharedMemorySize, SMEM_TOT);

    prep_act<<<(unsigned)(NBH / 1024), 256>>>(x, alpha, mk, mv, mr, out);
    prep_w<<<dim3((unsigned)(NHH / 1024), 4), 256>>>(Wk, Wv, Wr, Wo);

    dim3 g3(HDIM / BN, BDIM / BM, 3);
    gemm_mma<true><<<g3, GT, SMEM_TOT>>>(0, nullptr);

    ew_kernel<<<(unsigned)(NBH / 1024), 256>>>(aa, bb, pp, td, tf, out);

    dim3 g1(HDIM / BN, BDIM / BM, 1);
    gemm_mma<false><<<g1, GT, SMEM_TOT>>>(3, out);
}

// round 11
// speedup vs baseline: 1.1035x; 1.1035x over previous
#include <cuda_runtime.h>
#include <cuda_fp16.h>
#include <cstdint>

#define BDIM 16384
#define HDIM 1024
constexpr size_t NBH = (size_t)BDIM * HDIM;
constexpr size_t NHH = (size_t)HDIM * HDIM;

// ---------------------------------------------------------------------------
// Scratch (static device arrays: allocation-free per harness rules)
// ---------------------------------------------------------------------------
__device__ __align__(16) __half g_kh[NBH];
__device__ __align__(16) __half g_vh[NBH];
__device__ __align__(16) __half g_rh[NBH];

__device__ __align__(16) __half g_xk[NBH];
__device__ __align__(16) __half g_xv[NBH];
__device__ __align__(16) __half g_xr[NBH];
__device__ __align__(16) __half g_rw[NBH];

__device__ __align__(16) __half g_wk[NHH];
__device__ __align__(16) __half g_wv[NHH];
__device__ __align__(16) __half g_wr[NHH];
__device__ __align__(16) __half g_wo[NHH];

// ---------------------------------------------------------------------------
// PTX helpers (legal on base sm_103 target)
// ---------------------------------------------------------------------------
__device__ __forceinline__ uint32_t smem_u32(const void* p) {
    uint32_t a;
    asm("{ .reg .u64 t; cvta.to.shared.u64 t, %1; cvt.u32.u64 %0, t; }" : "=r"(a) : "l"(p));
    return a;
}
__device__ __forceinline__ void cp16(uint32_t dst, const void* src) {
    asm volatile("cp.async.cg.shared.global [%0], [%1], 16;" :: "r"(dst), "l"(src) : "memory");
}
__device__ __forceinline__ void cp_commit() {
    asm volatile("cp.async.commit_group;" ::: "memory");
}
__device__ __forceinline__ void ldsm4(uint32_t* r, uint32_t addr) {
    asm volatile("ldmatrix.sync.aligned.m8n8.x4.shared.b16 {%0,%1,%2,%3}, [%4];"
                 : "=r"(r[0]), "=r"(r[1]), "=r"(r[2]), "=r"(r[3]) : "r"(addr));
}
__device__ __forceinline__ void mma_f16(float* c, const uint32_t* a, uint32_t b0, uint32_t b1) {
    asm volatile(
        "mma.sync.aligned.m16n8k16.row.col.f32.f16.f16.f32 "
        "{%0,%1,%2,%3}, {%4,%5,%6,%7}, {%8,%9}, {%0,%1,%2,%3};"
        : "+f"(c[0]), "+f"(c[1]), "+f"(c[2]), "+f"(c[3])
        : "r"(a[0]), "r"(a[1]), "r"(a[2]), "r"(a[3]), "r"(b0), "r"(b1));
}

// ---------------------------------------------------------------------------
// GEMM config: CTA 128x128x64, 8 warps (4m x 2n -> warp tile 32x64), 3 stages
// (proven operating point: 2 CTAs/SM, 16 warps/SM)
// ---------------------------------------------------------------------------
constexpr int BM = 128, BN = 128, BK = 64;
constexpr int NCH = HDIM / BK;              // 16
constexpr int NSTG = 3;
constexpr int PLANE_B = BM * BK * 2;        // 16384 bytes
constexpr int STAGE_B = 2 * PLANE_B;        // 32768: [A][B]
constexpr int SMEM_TOT = NSTG * STAGE_B;    // 98304

// SW128: row stride 128B (8 x 16B chunks), chunk swizzled by row&7
__device__ __forceinline__ uint32_t swz_off(int row, int ch) {
    return (uint32_t)(row * 128 + ((ch ^ (row & 7)) << 4));
}

// ---------------------------------------------------------------------------
// fp16 GEMM: D[M,N] = A[M,K] @ W[N,K]^T
// which = base + blockIdx.z: 0=k, 1=v, 2=r (fp16 out), 3=out (fp32 out)
// R9 structure + 1-deep B-fragment ping-pong (hides LDSM->MMA RAW latency).
// ---------------------------------------------------------------------------
template <bool FP16OUT>
__global__ void __launch_bounds__(256, 2) gemm_mma(int base_which, float* __restrict__ outp)
{
    extern __shared__ __align__(1024) char smem[];
    const uint32_t sb = smem_u32(smem);
    const int tid = threadIdx.x;
    const int lane = tid & 31;
    const int warp = tid >> 5;
    const int wm = warp >> 1;              // 0..3
    const int wn = warp & 1;               // 0..1
    const int m0 = blockIdx.y * BM;
    const int n0 = blockIdx.x * BN;

    const int which = base_which + blockIdx.z;
    const __half *A, *B;
    __half* Dh = nullptr;
    float* Df = nullptr;
    if (which == 0)      { A = g_xk; B = g_wk; Dh = g_kh; }
    else if (which == 1) { A = g_xv; B = g_wv; Dh = g_vh; }
    else if (which == 2) { A = g_xr; B = g_wr; Dh = g_rh; }
    else                 { A = g_rw; B = g_wo; Df = outp; }

    float acc[2][8][4];
#pragma unroll
    for (int i = 0; i < 2; i++)
#pragma unroll
        for (int j = 0; j < 8; j++)
#pragma unroll
            for (int l = 0; l < 4; l++) acc[i][j][l] = 0.f;

    const __half* pl[2] = { A, B };
    const int rb[2] = { m0, n0 };

    auto fill = [&](int c) {
        const uint32_t base = sb + (c % NSTG) * STAGE_B;
        const int kt = c * BK;
#pragma unroll
        for (int t = 0; t < 2; t++) {
#pragma unroll
            for (int it = 0; it < 4; it++) {
                int q = it * 256 + tid;       // 0..1023
                int row = q >> 3;
                int ch = q & 7;
                const void* src = pl[t] + (size_t)(rb[t] + row) * HDIM + kt + ch * 8;
                cp16(base + t * PLANE_B + swz_off(row, ch), src);
            }
        }
        cp_commit();
    };

    // ldmatrix lane-address components (proven layout)
    const int lr = lane & 7;
    const int a_row_base = wm * 32 + ((lane >> 3) & 1) * 8 + lr;   // + i*16
    const int a_ch_base  = (lane >> 4);                            // + 2*kk
    const int b_row_base = wn * 64 + (lane >> 4) * 8 + lr;         // + jj*16
    const int b_ch_base  = ((lane >> 3) & 1);                      // + 2*kk

    auto compute = [&](int c) {
        const uint32_t base = sb + (c % NSTG) * STAGE_B;
#pragma unroll
        for (int kk = 0; kk < 4; kk++) {
            uint32_t A4[2][4];
            uint32_t B4[2][4];   // ping-pong
#pragma unroll
            for (int i = 0; i < 2; i++) {
                int row = a_row_base + i * 16;
                ldsm4(A4[i], base + swz_off(row, a_ch_base + 2 * kk));
            }
            ldsm4(B4[0], base + PLANE_B + swz_off(b_row_base, b_ch_base + 2 * kk));
#pragma unroll
            for (int jj = 0; jj < 4; jj++) {
                const uint32_t* Bc = B4[jj & 1];
                if (jj < 3) {
                    int rowb = b_row_base + (jj + 1) * 16;
                    ldsm4(B4[(jj + 1) & 1], base + PLANE_B + swz_off(rowb, b_ch_base + 2 * kk));
                }
#pragma unroll
                for (int i = 0; i < 2; i++) {
                    mma_f16(acc[i][2 * jj],     A4[i], Bc[0], Bc[1]);
                    mma_f16(acc[i][2 * jj + 1], A4[i], Bc[2], Bc[3]);
                }
            }
        }
    };

    // ---- 3-stage pipeline ----
    fill(0);
    fill(1);
    for (int c = 0; c < NCH; c++) {
        if (c < NCH - 1) asm volatile("cp.async.wait_group 1;" ::: "memory");
        else             asm volatile("cp.async.wait_group 0;" ::: "memory");
        __syncthreads();
        if (c + 2 < NCH) fill(c + 2);
        compute(c);
    }

    // ---- epilogue ----
#pragma unroll
    for (int i = 0; i < 2; i++) {
        int row = m0 + wm * 32 + i * 16 + (lane >> 2);
#pragma unroll
        for (int j = 0; j < 8; j++) {
            int col = n0 + wn * 64 + j * 8 + (lane & 3) * 2;
            if (FP16OUT) {
                *(__half2*)(Dh + (size_t)row * HDIM + col) =
                    __floats2half2_rn(acc[i][j][0], acc[i][j][1]);
                *(__half2*)(Dh + (size_t)(row + 8) * HDIM + col) =
                    __floats2half2_rn(acc[i][j][2], acc[i][j][3]);
            } else {
                float2 v0 = { acc[i][j][0], acc[i][j][1] };
                float2 v1 = { acc[i][j][2], acc[i][j][3] };
                *(float2*)(Df + (size_t)row * HDIM + col)       = v0;
                *(float2*)(Df + (size_t)(row + 8) * HDIM + col) = v1;
            }
        }
    }
}

// ---------------------------------------------------------------------------
// prep: blend token-shift mixes -> fp16 planes; also copy x -> out slot 1
// ---------------------------------------------------------------------------
__device__ __forceinline__ void blend_store(
    const float4& xv, const float4& av, const float4& m, __half* dst, size_t i)
{
    union { __half h[4]; uint2 u; } H;
    H.h[0] = __float2half_rn(xv.x * m.x + av.x * (1.f - m.x));
    H.h[1] = __float2half_rn(xv.y * m.y + av.y * (1.f - m.y));
    H.h[2] = __float2half_rn(xv.z * m.z + av.z * (1.f - m.z));
    H.h[3] = __float2half_rn(xv.w * m.w + av.w * (1.f - m.w));
    *(uint2*)(dst + i) = H.u;
}

__global__ void __launch_bounds__(256) prep_act(
    const float* __restrict__ x, const float* __restrict__ alpha,
    const float* __restrict__ mk, const float* __restrict__ mv,
    const float* __restrict__ mr, float* __restrict__ out)
{
    size_t i = ((size_t)blockIdx.x * 256 + threadIdx.x) * 4;
    int h = (int)(i & (HDIM - 1));
    float4 xv = *(const float4*)(x + i);
    float4 av = *(const float4*)(alpha + i);
    blend_store(xv, av, *(const float4*)(mk + h), g_xk, i);
    blend_store(xv, av, *(const float4*)(mv + h), g_xv, i);
    blend_store(xv, av, *(const float4*)(mr + h), g_xr, i);
    *(float4*)(out + NBH + i) = xv;   // slot 1: x passthrough
}

__global__ void __launch_bounds__(256) prep_w(
    const float* __restrict__ Wk, const float* __restrict__ Wv,
    const float* __restrict__ Wr, const float* __restrict__ Wo)
{
    const float* W;
    __half* hp;
    switch (blockIdx.y) {
        case 0: W = Wk; hp = g_wk; break;
        case 1: W = Wv; hp = g_wv; break;
        case 2: W = Wr; hp = g_wr; break;
        default: W = Wo; hp = g_wo; break;
    }
    size_t i = ((size_t)blockIdx.x * 256 + threadIdx.x) * 4;
    float4 w = *(const float4*)(W + i);
    union { __half h[4]; uint2 u; } H;
    H.h[0] = __float2half_rn(w.x);
    H.h[1] = __float2half_rn(w.y);
    H.h[2] = __float2half_rn(w.z);
    H.h[3] = __float2half_rn(w.w);
    *(uint2*)(hp + i) = H.u;
}

// ---------------------------------------------------------------------------
// Fused elementwise WKV + state update + r*wkv (fp16) + output stores
// ---------------------------------------------------------------------------
__global__ void __launch_bounds__(256) ew_kernel(
    const float* __restrict__ aa, const float* __restrict__ bb,
    const float* __restrict__ pp, const float* __restrict__ td,
    const float* __restrict__ tf, float* __restrict__ out)
{
    size_t i4 = (size_t)blockIdx.x * 256 + threadIdx.x;
    size_t i = i4 * 4;
    int h = (int)(i & (HDIM - 1));

    union { uint2 u; __half hh[4]; } KU, VU, RU;
    KU.u = *(const uint2*)(g_kh + i);
    VU.u = *(const uint2*)(g_vh + i);
    RU.u = *(const uint2*)(g_rh + i);

    float4 p4 = *(const float4*)(pp + i);
    float4 a4 = *(const float4*)(aa + i);
    float4 b4 = *(const float4*)(bb + i);
    float4 tf4 = *(const float4*)(tf + h);
    float4 td4 = *(const float4*)(td + h);

    float4 na4, nb4, q24;
    float* p = &p4.x;  float* a = &a4.x;  float* b = &b4.x;
    float* tff = &tf4.x; float* tdd = &td4.x;
    float* na = &na4.x; float* nb = &nb4.x; float* q2 = &q24.x;

    union { __half hh[4]; uint2 u; } RW;

#pragma unroll
    for (int j = 0; j < 4; j++) {
        float kk = __half2float(KU.hh[j]);
        float vv = __half2float(VU.hh[j]);
        float rp = __half2float(RU.hh[j]);
        float ww = tff[j] + kk;
        float qq = fmaxf(p[j], ww);
        float e1 = expf(p[j] - qq);
        float e2 = expf(ww - qq);
        float wkv = (e1 * a[j] + e2 * vv) / (e1 * b[j] + e2);
        float w2 = p[j] + tdd[j];
        float qb = fmaxf(w2, kk);
        float e1b = expf(w2 - qb);
        float e2b = expf(kk - qb);
        na[j] = e1b * a[j] + e2b * vv;
        nb[j] = e1b * b[j] + e2b;
        q2[j] = qb;
        float r = 1.f / (1.f + expf(-rp));
        RW.hh[j] = __float2half_rn(r * wkv);
    }

    *(uint2*)(g_rw + i) = RW.u;
    *(float4*)(out + 2 * NBH + i) = na4;  // slot 2: next_aa
    *(float4*)(out + 3 * NBH + i) = nb4;  // slot 3: next_bb
    *(float4*)(out + 4 * NBH + i) = q24;  // slot 4: qq2
}

// ---------------------------------------------------------------------------
extern "C" void kernel_launch(void* const* d_in, const int* in_sizes, int n_in,
                              void* d_out, int out_size)
{
    const float* x     = (const float*)d_in[0];
    const float* alpha = (const float*)d_in[1];
    const float* aa    = (const float*)d_in[2];
    const float* bb    = (const float*)d_in[3];
    const float* pp    = (const float*)d_in[4];
    const float* td    = (const float*)d_in[5];
    const float* tf    = (const float*)d_in[6];
    const float* mk    = (const float*)d_in[7];
    const float* mv    = (const float*)d_in[8];
    const float* mr    = (const float*)d_in[9];
    const float* Wk    = (const float*)d_in[10];
    const float* Wv    = (const float*)d_in[11];
    const float* Wr    = (const float*)d_in[12];
    const float* Wo    = (const float*)d_in[13];
    float* out = (float*)d_out;

    cudaFuncSetAttribute(gemm_mma<true>,  cudaFuncAttributeMaxDynamicSharedMemorySize, SMEM_TOT);
    cudaFuncSetAttribute(gemm_mma<false>, cudaFuncAttributeMaxDynamicSharedMemorySize, SMEM_TOT);

    prep_act<<<(unsigned)(NBH / 1024), 256>>>(x, alpha, mk, mv, mr, out);
    prep_w<<<dim3((unsigned)(NHH / 1024), 4), 256>>>(Wk, Wv, Wr, Wo);

    dim3 g3(HDIM / BN, BDIM / BM, 3);
    gemm_mma<true><<<g3, 256, SMEM_TOT>>>(0, nullptr);

    ew_kernel<<<(unsigned)(NBH / 1024), 256>>>(aa, bb, pp, td, tf, out);

    dim3 g1(HDIM / BN, BDIM / BM, 1);
    gemm_mma<false><<<g1, 256, SMEM_TOT>>>(3, out);
}

// round 12
// speedup vs baseline: 1.1756x; 1.0654x over previous
#include <cuda_runtime.h>
#include <cuda_fp16.h>
#include <cstdint>

#define BDIM 16384
#define HDIM 1024
constexpr size_t NBH = (size_t)BDIM * HDIM;
constexpr size_t NHH = (size_t)HDIM * HDIM;

// ---------------------------------------------------------------------------
// Scratch (static device arrays: allocation-free per harness rules)
// GEMM INPUT planes (g_x*, g_rw, g_w*) are stored TILED+SWIZZLED:
//   tile = 128 rows x 64 cols (16 KB), tiles ordered [row_blk][k_chunk],
//   within-tile byte off = r*128 + ((ch ^ (r&7))<<4) + (col&7)*2
// GEMM outputs (g_kh/g_vh/g_rh, final out) remain LINEAR.
// ---------------------------------------------------------------------------
__device__ __align__(16) __half g_kh[NBH];
__device__ __align__(16) __half g_vh[NBH];
__device__ __align__(16) __half g_rh[NBH];

__device__ __align__(16) __half g_xk[NBH];
__device__ __align__(16) __half g_xv[NBH];
__device__ __align__(16) __half g_xr[NBH];
__device__ __align__(16) __half g_rw[NBH];

__device__ __align__(16) __half g_wk[NHH];
__device__ __align__(16) __half g_wv[NHH];
__device__ __align__(16) __half g_wr[NHH];
__device__ __align__(16) __half g_wo[NHH];

// ---------------------------------------------------------------------------
// PTX helpers (sm_90-baseline features only; legal on sm_103 base target)
// ---------------------------------------------------------------------------
__device__ __forceinline__ uint32_t smem_u32(const void* p) {
    uint32_t a;
    asm("{ .reg .u64 t; cvta.to.shared.u64 t, %1; cvt.u32.u64 %0, t; }" : "=r"(a) : "l"(p));
    return a;
}
__device__ __forceinline__ void mbar_init(uint32_t a, uint32_t cnt) {
    asm volatile("mbarrier.init.shared.b64 [%0], %1;" :: "r"(a), "r"(cnt) : "memory");
}
__device__ __forceinline__ void mbar_expect_tx(uint32_t a, uint32_t bytes) {
    asm volatile("mbarrier.arrive.expect_tx.shared.b64 _, [%0], %1;"
                 :: "r"(a), "r"(bytes) : "memory");
}
__device__ __forceinline__ void mbar_wait(uint32_t a, uint32_t parity) {
    asm volatile(
        "{\n\t.reg .pred P;\n\t"
        "WL%=:\n\t"
        "mbarrier.try_wait.parity.acquire.cta.shared::cta.b64 P, [%0], %1, 0x989680;\n\t"
        "@P bra WD%=;\n\t"
        "bra WL%=;\n\t"
        "WD%=:\n\t}"
        :: "r"(a), "r"(parity) : "memory");
}
__device__ __forceinline__ void cp_bulk(uint32_t dst, const void* src, uint32_t bytes,
                                        uint32_t mbar) {
    asm volatile(
        "cp.async.bulk.shared::cluster.global.mbarrier::complete_tx::bytes [%0], [%1], %2, [%3];"
        :: "r"(dst), "l"(src), "r"(bytes), "r"(mbar) : "memory");
}
__device__ __forceinline__ void ldsm4(uint32_t* r, uint32_t addr) {
    asm volatile("ldmatrix.sync.aligned.m8n8.x4.shared.b16 {%0,%1,%2,%3}, [%4];"
                 : "=r"(r[0]), "=r"(r[1]), "=r"(r[2]), "=r"(r[3]) : "r"(addr));
}
__device__ __forceinline__ void mma_f16(float* c, const uint32_t* a, uint32_t b0, uint32_t b1) {
    asm volatile(
        "mma.sync.aligned.m16n8k16.row.col.f32.f16.f16.f32 "
        "{%0,%1,%2,%3}, {%4,%5,%6,%7}, {%8,%9}, {%0,%1,%2,%3};"
        : "+f"(c[0]), "+f"(c[1]), "+f"(c[2]), "+f"(c[3])
        : "r"(a[0]), "r"(a[1]), "r"(a[2]), "r"(a[3]), "r"(b0), "r"(b1));
}

// ---------------------------------------------------------------------------
// GEMM config: CTA 128x128x64, 8 warps (4m x 2n -> warp tile 32x64), 3 stages
// ---------------------------------------------------------------------------
constexpr int BM = 128, BN = 128, BK = 64;
constexpr int NCH = HDIM / BK;              // 16
constexpr int NSTG = 3;
constexpr int PLANE_B = BM * BK * 2;        // 16384 bytes (one tile)
constexpr int STAGE_B = 2 * PLANE_B;        // 32768: [A][B]
constexpr int SMEM_STAGES_OFF = 1024;       // barriers live below
constexpr int SMEM_TOT = SMEM_STAGES_OFF + NSTG * STAGE_B;  // 99328

// within-tile swizzled offset (bytes): row 0..127, 16B chunk 0..7
__device__ __forceinline__ uint32_t swz_off(int row, int ch) {
    return (uint32_t)(row * 128 + ((ch ^ (row & 7)) << 4));
}

// tiled global HALF-element offset for (row, col h)
__device__ __forceinline__ size_t tiled_off(size_t row, int h) {
    size_t tile = ((row >> 7) << 4) + (size_t)(h >> 6);
    int r = (int)(row & 127);
    int ch = (h & 63) >> 3;
    return tile * 8192 + (size_t)(r * 64 + ((ch ^ (r & 7)) << 3) + (h & 7));
}

// ---------------------------------------------------------------------------
// fp16 GEMM: D[M,N] = A[M,K] @ W[N,K]^T  (A, W tiled; bulk-copy fills)
// which = base + blockIdx.z: 0=k, 1=v, 2=r (fp16 out), 3=out (fp32 out)
// ---------------------------------------------------------------------------
template <bool FP16OUT>
__global__ void __launch_bounds__(256, 2) gemm_mma(int base_which, float* __restrict__ outp)
{
    extern __shared__ __align__(1024) char smem[];
    const uint32_t sb = smem_u32(smem);
    const uint32_t mb = sb;                       // 3 mbarriers at sb+0,8,16
    const uint32_t st = sb + SMEM_STAGES_OFF;
    const int tid = threadIdx.x;
    const int lane = tid & 31;
    const int warp = tid >> 5;
    const int wm = warp >> 1;              // 0..3
    const int wn = warp & 1;               // 0..1
    const int m0 = blockIdx.y * BM;
    const int n0 = blockIdx.x * BN;

    const int which = base_which + blockIdx.z;
    const __half *A, *B;
    __half* Dh = nullptr;
    float* Df = nullptr;
    if (which == 0)      { A = g_xk; B = g_wk; Dh = g_kh; }
    else if (which == 1) { A = g_xv; B = g_wv; Dh = g_vh; }
    else if (which == 2) { A = g_xr; B = g_wr; Dh = g_rh; }
    else                 { A = g_rw; B = g_wo; Df = outp; }

    float acc[2][8][4];
#pragma unroll
    for (int i = 0; i < 2; i++)
#pragma unroll
        for (int j = 0; j < 8; j++)
#pragma unroll
            for (int l = 0; l < 4; l++) acc[i][j][l] = 0.f;

    if (tid == 0) {
        mbar_init(mb + 0, 1);
        mbar_init(mb + 8, 1);
        mbar_init(mb + 16, 1);
    }
    __syncthreads();

    const size_t a_tile0 = ((size_t)(m0 >> 7)) << 4;   // + chunk
    const size_t b_tile0 = ((size_t)(n0 >> 7)) << 4;

    auto fill = [&](int c) {
        if (tid == 0) {
            const int s = c % NSTG;
            const uint32_t dst = st + s * STAGE_B;
            mbar_expect_tx(mb + s * 8, (uint32_t)STAGE_B);
            cp_bulk(dst,           A + (a_tile0 + c) * 8192, PLANE_B, mb + s * 8);
            cp_bulk(dst + PLANE_B, B + (b_tile0 + c) * 8192, PLANE_B, mb + s * 8);
        }
    };

    // ldmatrix lane-address components (proven layout)
    const int lr = lane & 7;
    const int a_row_base = wm * 32 + ((lane >> 3) & 1) * 8 + lr;   // + i*16
    const int a_ch_base  = (lane >> 4);                            // + 2*kk
    const int b_row_base = wn * 64 + (lane >> 4) * 8 + lr;         // + jj*16
    const int b_ch_base  = ((lane >> 3) & 1);                      // + 2*kk

    auto compute = [&](int c) {
        const uint32_t base = st + (c % NSTG) * STAGE_B;
#pragma unroll
        for (int kk = 0; kk < 4; kk++) {
            uint32_t A4[2][4];
            uint32_t B4[2][4];   // ping-pong
#pragma unroll
            for (int i = 0; i < 2; i++) {
                int row = a_row_base + i * 16;
                ldsm4(A4[i], base + swz_off(row, a_ch_base + 2 * kk));
            }
            ldsm4(B4[0], base + PLANE_B + swz_off(b_row_base, b_ch_base + 2 * kk));
#pragma unroll
            for (int jj = 0; jj < 4; jj++) {
                const uint32_t* Bc = B4[jj & 1];
                if (jj < 3) {
                    int rowb = b_row_base + (jj + 1) * 16;
                    ldsm4(B4[(jj + 1) & 1], base + PLANE_B + swz_off(rowb, b_ch_base + 2 * kk));
                }
#pragma unroll
                for (int i = 0; i < 2; i++) {
                    mma_f16(acc[i][2 * jj],     A4[i], Bc[0], Bc[1]);
                    mma_f16(acc[i][2 * jj + 1], A4[i], Bc[2], Bc[3]);
                }
            }
        }
    };

    // ---- 3-stage pipeline with bulk fills ----
    fill(0);
    fill(1);
    for (int c = 0; c < NCH; c++) {
        mbar_wait(mb + (c % NSTG) * 8, (uint32_t)((c / NSTG) & 1));
        compute(c);
        __syncthreads();
        if (c + 2 < NCH) fill(c + 2);
    }

    // ---- epilogue (linear outputs) ----
#pragma unroll
    for (int i = 0; i < 2; i++) {
        int row = m0 + wm * 32 + i * 16 + (lane >> 2);
#pragma unroll
        for (int j = 0; j < 8; j++) {
            int col = n0 + wn * 64 + j * 8 + (lane & 3) * 2;
            if (FP16OUT) {
                *(__half2*)(Dh + (size_t)row * HDIM + col) =
                    __floats2half2_rn(acc[i][j][0], acc[i][j][1]);
                *(__half2*)(Dh + (size_t)(row + 8) * HDIM + col) =
                    __floats2half2_rn(acc[i][j][2], acc[i][j][3]);
            } else {
                float2 v0 = { acc[i][j][0], acc[i][j][1] };
                float2 v1 = { acc[i][j][2], acc[i][j][3] };
                *(float2*)(Df + (size_t)row * HDIM + col)       = v0;
                *(float2*)(Df + (size_t)(row + 8) * HDIM + col) = v1;
            }
        }
    }
}

// ---------------------------------------------------------------------------
// prep: blend token-shift mixes -> TILED fp16 planes; copy x -> out slot 1
// ---------------------------------------------------------------------------
__device__ __forceinline__ void blend_store(
    const float4& xv, const float4& av, const float4& m, __half* dst, size_t toff)
{
    union { __half h[4]; uint2 u; } H;
    H.h[0] = __float2half_rn(xv.x * m.x + av.x * (1.f - m.x));
    H.h[1] = __float2half_rn(xv.y * m.y + av.y * (1.f - m.y));
    H.h[2] = __float2half_rn(xv.z * m.z + av.z * (1.f - m.z));
    H.h[3] = __float2half_rn(xv.w * m.w + av.w * (1.f - m.w));
    *(uint2*)(dst + toff) = H.u;
}

__global__ void __launch_bounds__(256) prep_act(
    const float* __restrict__ x, const float* __restrict__ alpha,
    const float* __restrict__ mk, const float* __restrict__ mv,
    const float* __restrict__ mr, float* __restrict__ out)
{
    size_t i = ((size_t)blockIdx.x * 256 + threadIdx.x) * 4;
    int h = (int)(i & (HDIM - 1));
    size_t toff = tiled_off(i >> 10, h);
    float4 xv = *(const float4*)(x + i);
    float4 av = *(const float4*)(alpha + i);
    blend_store(xv, av, *(const float4*)(mk + h), g_xk, toff);
    blend_store(xv, av, *(const float4*)(mv + h), g_xv, toff);
    blend_store(xv, av, *(const float4*)(mr + h), g_xr, toff);
    *(float4*)(out + NBH + i) = xv;   // slot 1: x passthrough
}

__global__ void __launch_bounds__(256) prep_w(
    const float* __restrict__ Wk, const float* __restrict__ Wv,
    const float* __restrict__ Wr, const float* __restrict__ Wo)
{
    const float* W;
    __half* hp;
    switch (blockIdx.y) {
        case 0: W = Wk; hp = g_wk; break;
        case 1: W = Wv; hp = g_wv; break;
        case 2: W = Wr; hp = g_wr; break;
        default: W = Wo; hp = g_wo; break;
    }
    size_t i = ((size_t)blockIdx.x * 256 + threadIdx.x) * 4;
    int h = (int)(i & (HDIM - 1));
    size_t toff = tiled_off(i >> 10, h);
    float4 w = *(const float4*)(W + i);
    union { __half hh[4]; uint2 u; } H;
    H.hh[0] = __float2half_rn(w.x);
    H.hh[1] = __float2half_rn(w.y);
    H.hh[2] = __float2half_rn(w.z);
    H.hh[3] = __float2half_rn(w.w);
    *(uint2*)(hp + toff) = H.u;
}

// ---------------------------------------------------------------------------
// Fused elementwise WKV + state update + r*wkv (fp16, TILED) + output stores
// ---------------------------------------------------------------------------
__global__ void __launch_bounds__(256) ew_kernel(
    const float* __restrict__ aa, const float* __restrict__ bb,
    const float* __restrict__ pp, const float* __restrict__ td,
    const float* __restrict__ tf, float* __restrict__ out)
{
    size_t i4 = (size_t)blockIdx.x * 256 + threadIdx.x;
    size_t i = i4 * 4;
    int h = (int)(i & (HDIM - 1));

    union { uint2 u; __half hh[4]; } KU, VU, RU;
    KU.u = *(const uint2*)(g_kh + i);
    VU.u = *(const uint2*)(g_vh + i);
    RU.u = *(const uint2*)(g_rh + i);

    float4 p4 = *(const float4*)(pp + i);
    float4 a4 = *(const float4*)(aa + i);
    float4 b4 = *(const float4*)(bb + i);
    float4 tf4 = *(const float4*)(tf + h);
    float4 td4 = *(const float4*)(td + h);

    float4 na4, nb4, q24;
    float* p = &p4.x;  float* a = &a4.x;  float* b = &b4.x;
    float* tff = &tf4.x; float* tdd = &td4.x;
    float* na = &na4.x; float* nb = &nb4.x; float* q2 = &q24.x;

    union { __half hh[4]; uint2 u; } RW;

#pragma unroll
    for (int j = 0; j < 4; j++) {
        float kk = __half2float(KU.hh[j]);
        float vv = __half2float(VU.hh[j]);
        float rp = __half2float(RU.hh[j]);
        float ww = tff[j] + kk;
        float qq = fmaxf(p[j], ww);
        float e1 = expf(p[j] - qq);
        float e2 = expf(ww - qq);
        float wkv = (e1 * a[j] + e2 * vv) / (e1 * b[j] + e2);
        float w2 = p[j] + tdd[j];
        float qb = fmaxf(w2, kk);
        float e1b = expf(w2 - qb);
        float e2b = expf(kk - qb);
        na[j] = e1b * a[j] + e2b * vv;
        nb[j] = e1b * b[j] + e2b;
        q2[j] = qb;
        float r = 1.f / (1.f + expf(-rp));
        RW.hh[j] = __float2half_rn(r * wkv);
    }

    *(uint2*)(g_rw + tiled_off(i >> 10, h)) = RW.u;
    *(float4*)(out + 2 * NBH + i) = na4;  // slot 2: next_aa
    *(float4*)(out + 3 * NBH + i) = nb4;  // slot 3: next_bb
    *(float4*)(out + 4 * NBH + i) = q24;  // slot 4: qq2
}

// ---------------------------------------------------------------------------
extern "C" void kernel_launch(void* const* d_in, const int* in_sizes, int n_in,
                              void* d_out, int out_size)
{
    const float* x     = (const float*)d_in[0];
    const float* alpha = (const float*)d_in[1];
    const float* aa    = (const float*)d_in[2];
    const float* bb    = (const float*)d_in[3];
    const float* pp    = (const float*)d_in[4];
    const float* td    = (const float*)d_in[5];
    const float* tf    = (const float*)d_in[6];
    const float* mk    = (const float*)d_in[7];
    const float* mv    = (const float*)d_in[8];
    const float* mr    = (const float*)d_in[9];
    const float* Wk    = (const float*)d_in[10];
    const float* Wv    = (const float*)d_in[11];
    const float* Wr    = (const float*)d_in[12];
    const float* Wo    = (const float*)d_in[13];
    float* out = (float*)d_out;

    cudaFuncSetAttribute(gemm_mma<true>,  cudaFuncAttributeMaxDynamicSharedMemorySize, SMEM_TOT);
    cudaFuncSetAttribute(gemm_mma<false>, cudaFuncAttributeMaxDynamicSharedMemorySize, SMEM_TOT);

    prep_act<<<(unsigned)(NBH / 1024), 256>>>(x, alpha, mk, mv, mr, out);
    prep_w<<<dim3((unsigned)(NHH / 1024), 4), 256>>>(Wk, Wv, Wr, Wo);

    dim3 g3(HDIM / BN, BDIM / BM, 3);
    gemm_mma<true><<<g3, 256, SMEM_TOT>>>(0, nullptr);

    ew_kernel<<<(unsigned)(NBH / 1024), 256>>>(aa, bb, pp, td, tf, out);

    dim3 g1(HDIM / BN, BDIM / BM, 1);
    gemm_mma<false><<<g1, 256, SMEM_TOT>>>(3, out);
}

// round 13
// speedup vs baseline: 1.1952x; 1.0167x over previous
#include <cuda_runtime.h>
#include <cuda_fp16.h>
#include <cstdint>

#define BDIM 16384
#define HDIM 1024
constexpr size_t NBH = (size_t)BDIM * HDIM;
constexpr size_t NHH = (size_t)HDIM * HDIM;

// ---------------------------------------------------------------------------
// Scratch (static device arrays: allocation-free per harness rules)
// GEMM INPUT planes (g_x*, g_rw, g_w*) are stored TILED+SWIZZLED:
//   tile = 128 rows x 64 cols (16 KB), tiles ordered [row_blk][k_chunk]
// GEMM outputs (g_kh/g_vh/g_rh, final out) remain LINEAR.
// ---------------------------------------------------------------------------
__device__ __align__(16) __half g_kh[NBH];
__device__ __align__(16) __half g_vh[NBH];
__device__ __align__(16) __half g_rh[NBH];

__device__ __align__(16) __half g_xk[NBH];
__device__ __align__(16) __half g_xv[NBH];
__device__ __align__(16) __half g_xr[NBH];
__device__ __align__(16) __half g_rw[NBH];

__device__ __align__(16) __half g_wk[NHH];
__device__ __align__(16) __half g_wv[NHH];
__device__ __align__(16) __half g_wr[NHH];
__device__ __align__(16) __half g_wo[NHH];

// ---------------------------------------------------------------------------
// PTX helpers (sm_90-baseline features only; legal on sm_103 base target)
// ---------------------------------------------------------------------------
__device__ __forceinline__ uint32_t smem_u32(const void* p) {
    uint32_t a;
    asm("{ .reg .u64 t; cvta.to.shared.u64 t, %1; cvt.u32.u64 %0, t; }" : "=r"(a) : "l"(p));
    return a;
}
__device__ __forceinline__ void mbar_init(uint32_t a, uint32_t cnt) {
    asm volatile("mbarrier.init.shared.b64 [%0], %1;" :: "r"(a), "r"(cnt) : "memory");
}
__device__ __forceinline__ void mbar_expect_tx(uint32_t a, uint32_t bytes) {
    asm volatile("mbarrier.arrive.expect_tx.shared.b64 _, [%0], %1;"
                 :: "r"(a), "r"(bytes) : "memory");
}
__device__ __forceinline__ void mbar_arrive(uint32_t a) {
    asm volatile("mbarrier.arrive.shared.b64 _, [%0];" :: "r"(a) : "memory");
}
__device__ __forceinline__ void mbar_wait(uint32_t a, uint32_t parity) {
    asm volatile(
        "{\n\t.reg .pred P;\n\t"
        "WL%=:\n\t"
        "mbarrier.try_wait.parity.acquire.cta.shared::cta.b64 P, [%0], %1, 0x989680;\n\t"
        "@P bra WD%=;\n\t"
        "bra WL%=;\n\t"
        "WD%=:\n\t}"
        :: "r"(a), "r"(parity) : "memory");
}
__device__ __forceinline__ void mbar_wait_relaxed(uint32_t a, uint32_t parity) {
    asm volatile(
        "{\n\t.reg .pred P;\n\t"
        "WL%=:\n\t"
        "mbarrier.try_wait.parity.relaxed.cta.shared::cta.b64 P, [%0], %1, 0x989680;\n\t"
        "@P bra WD%=;\n\t"
        "bra WL%=;\n\t"
        "WD%=:\n\t}"
        :: "r"(a), "r"(parity) : "memory");
}
__device__ __forceinline__ void cp_bulk(uint32_t dst, const void* src, uint32_t bytes,
                                        uint32_t mbar) {
    asm volatile(
        "cp.async.bulk.shared::cluster.global.mbarrier::complete_tx::bytes [%0], [%1], %2, [%3];"
        :: "r"(dst), "l"(src), "r"(bytes), "r"(mbar) : "memory");
}
__device__ __forceinline__ void ldsm4(uint32_t* r, uint32_t addr) {
    asm volatile("ldmatrix.sync.aligned.m8n8.x4.shared.b16 {%0,%1,%2,%3}, [%4];"
                 : "=r"(r[0]), "=r"(r[1]), "=r"(r[2]), "=r"(r[3]) : "r"(addr));
}
__device__ __forceinline__ void mma_f16(float* c, const uint32_t* a, uint32_t b0, uint32_t b1) {
    asm volatile(
        "mma.sync.aligned.m16n8k16.row.col.f32.f16.f16.f32 "
        "{%0,%1,%2,%3}, {%4,%5,%6,%7}, {%8,%9}, {%0,%1,%2,%3};"
        : "+f"(c[0]), "+f"(c[1]), "+f"(c[2]), "+f"(c[3])
        : "r"(a[0]), "r"(a[1]), "r"(a[2]), "r"(a[3]), "r"(b0), "r"(b1));
}

// ---------------------------------------------------------------------------
// GEMM config: CTA 128x128x64, 8 warps (4m x 2n -> warp tile 32x64), 3 stages
// ---------------------------------------------------------------------------
constexpr int BM = 128, BN = 128, BK = 64;
constexpr int NCH = HDIM / BK;              // 16
constexpr int NSTG = 3;
constexpr int PLANE_B = BM * BK * 2;        // 16384 bytes (one tile)
constexpr int STAGE_B = 2 * PLANE_B;        // 32768: [A][B]
constexpr int SMEM_STAGES_OFF = 1024;       // barriers live below
constexpr int SMEM_TOT = SMEM_STAGES_OFF + NSTG * STAGE_B;  // 99328

// within-tile swizzled offset (bytes): row 0..127, 16B chunk 0..7
__device__ __forceinline__ uint32_t swz_off(int row, int ch) {
    return (uint32_t)(row * 128 + ((ch ^ (row & 7)) << 4));
}

// tiled global HALF-element offset for (row, col h)
__device__ __forceinline__ size_t tiled_off(size_t row, int h) {
    size_t tile = ((row >> 7) << 4) + (size_t)(h >> 6);
    int r = (int)(row & 127);
    int ch = (h & 63) >> 3;
    return tile * 8192 + (size_t)(r * 64 + ((ch ^ (r & 7)) << 3) + (h & 7));
}

// ---------------------------------------------------------------------------
// fp16 GEMM: D[M,N] = A[M,K] @ W[N,K]^T  (A, W tiled; bulk fills; full/empty
// mbarrier pipeline -- NO per-chunk __syncthreads)
// which = base + blockIdx.z: 0=k, 1=v, 2=r (fp16 out), 3=out (fp32 out)
// ---------------------------------------------------------------------------
template <bool FP16OUT>
__global__ void __launch_bounds__(256, 2) gemm_mma(int base_which, float* __restrict__ outp)
{
    extern __shared__ __align__(1024) char smem[];
    const uint32_t sb = smem_u32(smem);
    const uint32_t fullb = sb;                 // full[s] at sb + s*8
    const uint32_t emptb = sb + 24;            // empty[s] at sb+24 + s*8
    const uint32_t st = sb + SMEM_STAGES_OFF;
    const int tid = threadIdx.x;
    const int lane = tid & 31;
    const int warp = tid >> 5;
    const int wm = warp >> 1;              // 0..3
    const int wn = warp & 1;               // 0..1
    const int m0 = blockIdx.y * BM;
    const int n0 = blockIdx.x * BN;

    const int which = base_which + blockIdx.z;
    const __half *A, *B;
    __half* Dh = nullptr;
    float* Df = nullptr;
    if (which == 0)      { A = g_xk; B = g_wk; Dh = g_kh; }
    else if (which == 1) { A = g_xv; B = g_wv; Dh = g_vh; }
    else if (which == 2) { A = g_xr; B = g_wr; Dh = g_rh; }
    else                 { A = g_rw; B = g_wo; Df = outp; }

    float acc[2][8][4];
#pragma unroll
    for (int i = 0; i < 2; i++)
#pragma unroll
        for (int j = 0; j < 8; j++)
#pragma unroll
            for (int l = 0; l < 4; l++) acc[i][j][l] = 0.f;

    if (tid == 0) {
#pragma unroll
        for (int s = 0; s < NSTG; s++) {
            mbar_init(fullb + s * 8, 1);
            mbar_init(emptb + s * 8, 8);
        }
    }
    __syncthreads();

    const size_t a_tile0 = ((size_t)(m0 >> 7)) << 4;   // + chunk
    const size_t b_tile0 = ((size_t)(n0 >> 7)) << 4;

    auto issue_fill = [&](int f) {
        const int s = f % NSTG;
        const uint32_t dst = st + s * STAGE_B;
        mbar_expect_tx(fullb + s * 8, (uint32_t)STAGE_B);
        cp_bulk(dst,           A + (a_tile0 + f) * 8192, PLANE_B, fullb + s * 8);
        cp_bulk(dst + PLANE_B, B + (b_tile0 + f) * 8192, PLANE_B, fullb + s * 8);
    };

    // prologue: stages fresh -> no empty wait needed
    if (tid == 0) { issue_fill(0); issue_fill(1); }

    // ldmatrix lane-address components (proven layout)
    const int lr = lane & 7;
    const int a_row_base = wm * 32 + ((lane >> 3) & 1) * 8 + lr;   // + i*16
    const int a_ch_base  = (lane >> 4);                            // + 2*kk
    const int b_row_base = wn * 64 + (lane >> 4) * 8 + lr;         // + jj*16
    const int b_ch_base  = ((lane >> 3) & 1);                      // + 2*kk

    auto compute = [&](int c) {
        const uint32_t base = st + (c % NSTG) * STAGE_B;
#pragma unroll
        for (int kk = 0; kk < 4; kk++) {
            uint32_t A4[2][4];
            uint32_t B4[2][4];   // ping-pong
#pragma unroll
            for (int i = 0; i < 2; i++) {
                int row = a_row_base + i * 16;
                ldsm4(A4[i], base + swz_off(row, a_ch_base + 2 * kk));
            }
            ldsm4(B4[0], base + PLANE_B + swz_off(b_row_base, b_ch_base + 2 * kk));
#pragma unroll
            for (int jj = 0; jj < 4; jj++) {
                const uint32_t* Bc = B4[jj & 1];
                if (jj < 3) {
                    int rowb = b_row_base + (jj + 1) * 16;
                    ldsm4(B4[(jj + 1) & 1], base + PLANE_B + swz_off(rowb, b_ch_base + 2 * kk));
                }
#pragma unroll
                for (int i = 0; i < 2; i++) {
                    mma_f16(acc[i][2 * jj],     A4[i], Bc[0], Bc[1]);
                    mma_f16(acc[i][2 * jj + 1], A4[i], Bc[2], Bc[3]);
                }
            }
        }
    };

    // ---- pipeline: full/empty barriers, no per-chunk __syncthreads ----
    for (int c = 0; c < NCH; c++) {
        const int s = c % NSTG;
        if (tid == 0) {
            int f = c + 2;
            if (f < NCH) {
                int sf = f % NSTG;
                if (f >= NSTG) {
                    // wait until all 8 warps consumed the previous tenant of sf
                    mbar_wait_relaxed(emptb + sf * 8, (uint32_t)(((f / NSTG) + 1) & 1));
                }
                issue_fill(f);
            }
        }
        mbar_wait(fullb + s * 8, (uint32_t)((c / NSTG) & 1));
        compute(c);
        if (lane == 0) mbar_arrive(emptb + s * 8);
    }

    // ---- epilogue (linear outputs) ----
#pragma unroll
    for (int i = 0; i < 2; i++) {
        int row = m0 + wm * 32 + i * 16 + (lane >> 2);
#pragma unroll
        for (int j = 0; j < 8; j++) {
            int col = n0 + wn * 64 + j * 8 + (lane & 3) * 2;
            if (FP16OUT) {
                *(__half2*)(Dh + (size_t)row * HDIM + col) =
                    __floats2half2_rn(acc[i][j][0], acc[i][j][1]);
                *(__half2*)(Dh + (size_t)(row + 8) * HDIM + col) =
                    __floats2half2_rn(acc[i][j][2], acc[i][j][3]);
            } else {
                float2 v0 = { acc[i][j][0], acc[i][j][1] };
                float2 v1 = { acc[i][j][2], acc[i][j][3] };
                *(float2*)(Df + (size_t)row * HDIM + col)       = v0;
                *(float2*)(Df + (size_t)(row + 8) * HDIM + col) = v1;
            }
        }
    }
}

// ---------------------------------------------------------------------------
// prep: blend token-shift mixes -> TILED fp16 planes; copy x -> out slot 1
// ---------------------------------------------------------------------------
__device__ __forceinline__ void blend_store(
    const float4& xv, const float4& av, const float4& m, __half* dst, size_t toff)
{
    union { __half h[4]; uint2 u; } H;
    H.h[0] = __float2half_rn(xv.x * m.x + av.x * (1.f - m.x));
    H.h[1] = __float2half_rn(xv.y * m.y + av.y * (1.f - m.y));
    H.h[2] = __float2half_rn(xv.z * m.z + av.z * (1.f - m.z));
    H.h[3] = __float2half_rn(xv.w * m.w + av.w * (1.f - m.w));
    *(uint2*)(dst + toff) = H.u;
}

__global__ void __launch_bounds__(256) prep_act(
    const float* __restrict__ x, const float* __restrict__ alpha,
    const float* __restrict__ mk, const float* __restrict__ mv,
    const float* __restrict__ mr, float* __restrict__ out)
{
    size_t i = ((size_t)blockIdx.x * 256 + threadIdx.x) * 4;
    int h = (int)(i & (HDIM - 1));
    size_t toff = tiled_off(i >> 10, h);
    float4 xv = *(const float4*)(x + i);
    float4 av = *(const float4*)(alpha + i);
    blend_store(xv, av, *(const float4*)(mk + h), g_xk, toff);
    blend_store(xv, av, *(const float4*)(mv + h), g_xv, toff);
    blend_store(xv, av, *(const float4*)(mr + h), g_xr, toff);
    *(float4*)(out + NBH + i) = xv;   // slot 1: x passthrough
}

__global__ void __launch_bounds__(256) prep_w(
    const float* __restrict__ Wk, const float* __restrict__ Wv,
    const float* __restrict__ Wr, const float* __restrict__ Wo)
{
    const float* W;
    __half* hp;
    switch (blockIdx.y) {
        case 0: W = Wk; hp = g_wk; break;
        case 1: W = Wv; hp = g_wv; break;
        case 2: W = Wr; hp = g_wr; break;
        default: W = Wo; hp = g_wo; break;
    }
    size_t i = ((size_t)blockIdx.x * 256 + threadIdx.x) * 4;
    int h = (int)(i & (HDIM - 1));
    size_t toff = tiled_off(i >> 10, h);
    float4 w = *(const float4*)(W + i);
    union { __half hh[4]; uint2 u; } H;
    H.hh[0] = __float2half_rn(w.x);
    H.hh[1] = __float2half_rn(w.y);
    H.hh[2] = __float2half_rn(w.z);
    H.hh[3] = __float2half_rn(w.w);
    *(uint2*)(hp + toff) = H.u;
}

// ---------------------------------------------------------------------------
// Fused elementwise WKV + state update + r*wkv (fp16, TILED) + output stores
// ---------------------------------------------------------------------------
__global__ void __launch_bounds__(256) ew_kernel(
    const float* __restrict__ aa, const float* __restrict__ bb,
    const float* __restrict__ pp, const float* __restrict__ td,
    const float* __restrict__ tf, float* __restrict__ out)
{
    size_t i4 = (size_t)blockIdx.x * 256 + threadIdx.x;
    size_t i = i4 * 4;
    int h = (int)(i & (HDIM - 1));

    union { uint2 u; __half hh[4]; } KU, VU, RU;
    KU.u = *(const uint2*)(g_kh + i);
    VU.u = *(const uint2*)(g_vh + i);
    RU.u = *(const uint2*)(g_rh + i);

    float4 p4 = *(const float4*)(pp + i);
    float4 a4 = *(const float4*)(aa + i);
    float4 b4 = *(const float4*)(bb + i);
    float4 tf4 = *(const float4*)(tf + h);
    float4 td4 = *(const float4*)(td + h);

    float4 na4, nb4, q24;
    float* p = &p4.x;  float* a = &a4.x;  float* b = &b4.x;
    float* tff = &tf4.x; float* tdd = &td4.x;
    float* na = &na4.x; float* nb = &nb4.x; float* q2 = &q24.x;

    union { __half hh[4]; uint2 u; } RW;

#pragma unroll
    for (int j = 0; j < 4; j++) {
        float kk = __half2float(KU.hh[j]);
        float vv = __half2float(VU.hh[j]);
        float rp = __half2float(RU.hh[j]);
        float ww = tff[j] + kk;
        float qq = fmaxf(p[j], ww);
        float e1 = expf(p[j] - qq);
        float e2 = expf(ww - qq);
        float wkv = (e1 * a[j] + e2 * vv) / (e1 * b[j] + e2);
        float w2 = p[j] + tdd[j];
        float qb = fmaxf(w2, kk);
        float e1b = expf(w2 - qb);
        float e2b = expf(kk - qb);
        na[j] = e1b * a[j] + e2b * vv;
        nb[j] = e1b * b[j] + e2b;
        q2[j] = qb;
        float r = 1.f / (1.f + expf(-rp));
        RW.hh[j] = __float2half_rn(r * wkv);
    }

    *(uint2*)(g_rw + tiled_off(i >> 10, h)) = RW.u;
    *(float4*)(out + 2 * NBH + i) = na4;  // slot 2: next_aa
    *(float4*)(out + 3 * NBH + i) = nb4;  // slot 3: next_bb
    *(float4*)(out + 4 * NBH + i) = q24;  // slot 4: qq2
}

// ---------------------------------------------------------------------------
extern "C" void kernel_launch(void* const* d_in, const int* in_sizes, int n_in,
                              void* d_out, int out_size)
{
    const float* x     = (const float*)d_in[0];
    const float* alpha = (const float*)d_in[1];
    const float* aa    = (const float*)d_in[2];
    const float* bb    = (const float*)d_in[3];
    const float* pp    = (const float*)d_in[4];
    const float* td    = (const float*)d_in[5];
    const float* tf    = (const float*)d_in[6];
    const float* mk    = (const float*)d_in[7];
    const float* mv    = (const float*)d_in[8];
    const float* mr    = (const float*)d_in[9];
    const float* Wk    = (const float*)d_in[10];
    const float* Wv    = (const float*)d_in[11];
    const float* Wr    = (const float*)d_in[12];
    const float* Wo    = (const float*)d_in[13];
    float* out = (float*)d_out;

    cudaFuncSetAttribute(gemm_mma<true>,  cudaFuncAttributeMaxDynamicSharedMemorySize, SMEM_TOT);
    cudaFuncSetAttribute(gemm_mma<false>, cudaFuncAttributeMaxDynamicSharedMemorySize, SMEM_TOT);

    prep_act<<<(unsigned)(NBH / 1024), 256>>>(x, alpha, mk, mv, mr, out);
    prep_w<<<dim3((unsigned)(NHH / 1024), 4), 256>>>(Wk, Wv, Wr, Wo);

    dim3 g3(HDIM / BN, BDIM / BM, 3);
    gemm_mma<true><<<g3, 256, SMEM_TOT>>>(0, nullptr);

    ew_kernel<<<(unsigned)(NBH / 1024), 256>>>(aa, bb, pp, td, tf, out);

    dim3 g1(HDIM / BN, BDIM / BM, 1);
    gemm_mma<false><<<g1, 256, SMEM_TOT>>>(3, out);
}